// round 4
// baseline (speedup 1.0000x reference)
#include <cuda_runtime.h>
#include <cuda_bf16.h>
#include <math.h>

// ---------------------------------------------------------------------------
// LLaDA router: logits = x @ W^T  (N=B*S tokens, D feat, E=8 experts)
//   -> LayerNorm(E) -> /(|T|+1e-6) -> softmax -> top-2 dispatch
//   -> router_loss = 0.01*mean(rl^2) + 0.01*KL(ideal||actual)/E
// Out layout: [routing_weights N*E][dispatch N*E][loss 1]
// Single fused kernel; last block (atomic ticket) reduces the loss.
//
// f32x2 accumulators packed over d-parity: {even-d sum, odd-d sum}. Both
// FFMA2 operands are adjacent pairs straight out of LDG.128 -> no pack MOVs.
// ---------------------------------------------------------------------------

#define EXPERTS 8
#define TOK_PER_WARP 4
#define WARPS_PER_BLOCK 8
#define TOK_PER_BLOCK (TOK_PER_WARP * WARPS_PER_BLOCK)   // 32
#define MAX_BLOCKS 8192

__device__ float g_part[MAX_BLOCKS * 9];
__device__ unsigned int g_ctr = 0;

typedef unsigned long long u64;

// acc.{lo,hi} += {xlo,xhi} * {wlo,whi}  (pair-movs coalesce when sources are
// adjacent vector-load registers)
__device__ __forceinline__ void fma2p(u64& acc, float xlo, float xhi,
                                      float wlo, float whi) {
    asm("{\n\t"
        ".reg .b64 xp, wp;\n\t"
        "mov.b64 xp, {%1, %2};\n\t"
        "mov.b64 wp, {%3, %4};\n\t"
        "fma.rn.f32x2 %0, xp, wp, %0;\n\t"
        "}"
        : "+l"(acc) : "f"(xlo), "f"(xhi), "f"(wlo), "f"(whi));
}
__device__ __forceinline__ void unpk2(u64 v, float& lo, float& hi) {
    asm("mov.b64 {%0, %1}, %2;" : "=f"(lo), "=f"(hi) : "l"(v));
}

template <int DD>   // DD = compile-time D (2048 fast path), 0 = runtime D
__global__ __launch_bounds__(256, 2)
void router_main(const float* __restrict__ x,
                 const float* __restrict__ W,
                 const float* __restrict__ gamma,
                 const float* __restrict__ beta,
                 const float* __restrict__ temp,
                 float* __restrict__ out,
                 int N, int Drt)
{
    const int D = DD ? DD : Drt;
    const int Dq = D >> 2;              // D in float4 units

    __shared__ float s_logits[TOK_PER_BLOCK * EXPERTS];
    __shared__ bool s_last;

    const int lane = threadIdx.x & 31;
    const int warp = threadIdx.x >> 5;
    const int tok0 = blockIdx.x * TOK_PER_BLOCK + warp * TOK_PER_WARP;

    const float4* xq[TOK_PER_WARP];
#pragma unroll
    for (int t = 0; t < TOK_PER_WARP; ++t) {
        int tt = min(tok0 + t, N - 1);          // clamp tail (dup work, masked)
        xq[t] = (const float4*)x + (size_t)tt * Dq + lane;
    }
    const float4* wq = (const float4*)W + lane;

    u64 acc[TOK_PER_WARP][EXPERTS];
#pragma unroll
    for (int t = 0; t < TOK_PER_WARP; ++t)
#pragma unroll
        for (int e = 0; e < EXPERTS; ++e) acc[t][e] = 0ull;

    float4 xc[TOK_PER_WARP];
#pragma unroll
    for (int t = 0; t < TOK_PER_WARP; ++t) xc[t] = __ldg(xq[t]);

    const int nIter = D >> 7;   // warp covers 128 floats per sweep

#pragma unroll 2
    for (int i = 0; i < nIter - 1; ++i) {
        // prefetch next x tile
        float4 xn[TOK_PER_WARP];
#pragma unroll
        for (int t = 0; t < TOK_PER_WARP; ++t) {
            xq[t] += 32;
            xn[t] = __ldg(xq[t]);
        }
        // two expert-halves of W (L1-resident)
#pragma unroll
        for (int h = 0; h < 2; ++h) {
            float4 wv[4];
#pragma unroll
            for (int e = 0; e < 4; ++e)
                wv[e] = __ldg(wq + (size_t)(h * 4 + e) * Dq);
#pragma unroll
            for (int t = 0; t < TOK_PER_WARP; ++t)
#pragma unroll
                for (int e = 0; e < 4; ++e) {
                    fma2p(acc[t][h * 4 + e], xc[t].x, xc[t].y, wv[e].x, wv[e].y);
                    fma2p(acc[t][h * 4 + e], xc[t].z, xc[t].w, wv[e].z, wv[e].w);
                }
        }
        wq += 32;
#pragma unroll
        for (int t = 0; t < TOK_PER_WARP; ++t) xc[t] = xn[t];
    }
    // peeled last iteration (no prefetch)
#pragma unroll
    for (int h = 0; h < 2; ++h) {
        float4 wv[4];
#pragma unroll
        for (int e = 0; e < 4; ++e)
            wv[e] = __ldg(wq + (size_t)(h * 4 + e) * Dq);
#pragma unroll
        for (int t = 0; t < TOK_PER_WARP; ++t)
#pragma unroll
            for (int e = 0; e < 4; ++e) {
                fma2p(acc[t][h * 4 + e], xc[t].x, xc[t].y, wv[e].x, wv[e].y);
                fma2p(acc[t][h * 4 + e], xc[t].z, xc[t].w, wv[e].z, wv[e].w);
            }
    }

    // fold d-parity halves, then butterfly-reduce 32 scalars across the warp
    float s[TOK_PER_WARP][EXPERTS];
#pragma unroll
    for (int t = 0; t < TOK_PER_WARP; ++t)
#pragma unroll
        for (int e = 0; e < EXPERTS; ++e) {
            float lo, hi;
            unpk2(acc[t][e], lo, hi);
            s[t][e] = lo + hi;
        }
#pragma unroll
    for (int m = 16; m >= 1; m >>= 1)
#pragma unroll
        for (int t = 0; t < TOK_PER_WARP; ++t)
#pragma unroll
            for (int e = 0; e < EXPERTS; ++e)
                s[t][e] += __shfl_xor_sync(0xFFFFFFFFu, s[t][e], m);

    if (lane == 0) {
#pragma unroll
        for (int t = 0; t < TOK_PER_WARP; ++t)
#pragma unroll
            for (int e = 0; e < EXPERTS; ++e)
                s_logits[(warp * TOK_PER_WARP + t) * EXPERTS + e] = s[t][e];
    }
    __syncthreads();

    // ---- epilogue: warp 0 handles the block's 32 tokens -------------------
    if (threadIdx.x < TOK_PER_BLOCK) {
        const int lt = threadIdx.x;
        const int g = blockIdx.x * TOK_PER_BLOCK + lt;
        const bool valid = (g < N);

        const float tinv = 1.0f / (fabsf(temp[0]) + 1e-6f);
        float gm[EXPERTS], bt[EXPERTS];
#pragma unroll
        for (int e = 0; e < EXPERTS; ++e) { gm[e] = gamma[e]; bt[e] = beta[e]; }

        float l[EXPERTS];
        float mu = 0.0f;
#pragma unroll
        for (int e = 0; e < EXPERTS; ++e) {
            l[e] = s_logits[lt * EXPERTS + e];
            mu += l[e];
        }
        mu *= (1.0f / EXPERTS);
        float var = 0.0f;
#pragma unroll
        for (int e = 0; e < EXPERTS; ++e) {
            float dlt = l[e] - mu;
            var += dlt * dlt;
        }
        var *= (1.0f / EXPERTS);
        const float rinv = rsqrtf(var + 1e-5f);

        float rl[EXPERTS];
        float zsum = 0.0f;
        float mx = -1e30f;
#pragma unroll
        for (int e = 0; e < EXPERTS; ++e) {
            float v = ((l[e] - mu) * rinv * gm[e] + bt[e]) * tinv;
            rl[e] = v;
            zsum += v * v;
            mx = fmaxf(mx, v);
        }
        float rw[EXPERTS];
        float ssum = 0.0f;
#pragma unroll
        for (int e = 0; e < EXPERTS; ++e) {
            rw[e] = expf(rl[e] - mx);
            ssum += rw[e];
        }
        const float sinv = 1.0f / ssum;
#pragma unroll
        for (int e = 0; e < EXPERTS; ++e) rw[e] *= sinv;

        // top-2 (lowest index wins ties, matching lax.top_k)
        int i1 = 0; float w1 = rw[0];
#pragma unroll
        for (int e = 1; e < EXPERTS; ++e)
            if (rw[e] > w1) { w1 = rw[e]; i1 = e; }
        int i2 = -1; float w2 = -1.0f;
#pragma unroll
        for (int e = 0; e < EXPERTS; ++e)
            if (e != i1 && rw[e] > w2) { w2 = rw[e]; i2 = e; }
        const float nrm = 1.0f / (w1 + w2 + 1e-6f);
        const float d1 = w1 * nrm, d2 = w2 * nrm;

        if (valid) {
            const size_t NE = (size_t)N * EXPERTS;
            float4* rwo = (float4*)(out + (size_t)g * EXPERTS);
            rwo[0] = make_float4(rw[0], rw[1], rw[2], rw[3]);
            rwo[1] = make_float4(rw[4], rw[5], rw[6], rw[7]);
            float disp[EXPERTS];
#pragma unroll
            for (int e = 0; e < EXPERTS; ++e)
                disp[e] = (e == i1) ? d1 : (e == i2) ? d2 : 0.0f;
            float4* dpo = (float4*)(out + NE + (size_t)g * EXPERTS);
            dpo[0] = make_float4(disp[0], disp[1], disp[2], disp[3]);
            dpo[1] = make_float4(disp[4], disp[5], disp[6], disp[7]);
        }

        // block partials (deterministic: warp reduce then single store)
        float zc = valid ? zsum : 0.0f;
        float ec[EXPERTS];
#pragma unroll
        for (int e = 0; e < EXPERTS; ++e) ec[e] = valid ? rw[e] : 0.0f;

#pragma unroll
        for (int m = 16; m >= 1; m >>= 1) {
            zc += __shfl_xor_sync(0xFFFFFFFFu, zc, m);
#pragma unroll
            for (int e = 0; e < EXPERTS; ++e)
                ec[e] += __shfl_xor_sync(0xFFFFFFFFu, ec[e], m);
        }
        if (lane == 0) {
            float* p = &g_part[(size_t)blockIdx.x * 9];
#pragma unroll
            for (int e = 0; e < EXPERTS; ++e) p[e] = ec[e];
            p[8] = zc;
        }
    }

    // ---- fused loss: last block reduces all partials ----------------------
    __syncthreads();
    if (threadIdx.x == 0) {
        __threadfence();
        unsigned int t = atomicAdd(&g_ctr, 1u);
        s_last = (t == gridDim.x - 1);
    }
    __syncthreads();

    if (s_last) {
        __shared__ float s_red[9];
        const int nb = gridDim.x;
        for (int c = warp; c < 9; c += WARPS_PER_BLOCK) {
            float v = 0.0f;
            for (int k = lane; k < nb; k += 32) v += g_part[(size_t)k * 9 + c];
#pragma unroll
            for (int m = 16; m >= 1; m >>= 1)
                v += __shfl_xor_sync(0xFFFFFFFFu, v, m);
            if (lane == 0) s_red[c] = v;
        }
        __syncthreads();
        if (threadIdx.x == 0) {
            const float invN = 1.0f / (float)N;
            float z = s_red[8] * invN * (1.0f / EXPERTS);
            float lb = 0.0f;
            const float ideal = 1.0f / EXPERTS;
#pragma unroll
            for (int e = 0; e < EXPERTS; ++e) {
                float actual = s_red[e] * invN;
                lb += ideal * (logf(ideal) - logf(actual));
            }
            lb *= (1.0f / EXPERTS);
            out[(size_t)2 * N * EXPERTS] = 0.01f * z + 0.01f * lb;
            g_ctr = 0;   // reset for next graph replay (deterministic)
        }
    }
}

extern "C" void kernel_launch(void* const* d_in, const int* in_sizes, int n_in,
                              void* d_out, int out_size)
{
    const float* x     = (const float*)d_in[0];
    const float* W     = (const float*)d_in[1];
    const float* gamma = (const float*)d_in[2];
    const float* beta  = (const float*)d_in[3];
    const float* temp  = (const float*)d_in[4];
    float* out = (float*)d_out;

    const int E = in_sizes[2];           // 8
    const int D = in_sizes[1] / E;       // 2048
    const int N = in_sizes[0] / D;       // 16384

    const int nb = (N + TOK_PER_BLOCK - 1) / TOK_PER_BLOCK;

    if (D == 2048)
        router_main<2048><<<nb, 256>>>(x, W, gamma, beta, temp, out, N, D);
    else
        router_main<0><<<nb, 256>>>(x, W, gamma, beta, temp, out, N, D);
}